// round 14
// baseline (speedup 1.0000x reference)
#include <cuda_runtime.h>
#include <cuda_fp16.h>
#include <math.h>
#include <stdint.h>

#define B_    8
#define N_    1024
#define NP_   512            // column pairs
#define NCTA  16             // CTAs per batch == hardware cluster size
#define GRID_ (B_ * NCTA)    // 128 CTAs
#define ROWS  64             // rows per CTA (uniform — no tail)
#define ITERS 10             // q=0.35: residual q^10 ~ 2.8e-5 ~ fp16 noise floor
#define PRECISE_FROM (ITERS - 2)
#define RINV  (1.0f / 1024.0f)
#define LMB   10.0f

// SMEM byte offsets
#define Z_B      0                      // float  z_s[1024]
#define U_B      4096                   // float  u_s[64]
#define ZH2_B    4352                   // half2  zh2[512]
#define WPART_B  6400                   // half2  wpart[16][32]  (src-major)
#define WPARTF_B 8448                   // float2 wpartf[16][32]
#define ZSL_B    12544                  // float2 zsl[32] (owner's z slice)
#define K_B      12800                  // half   Ksh[64*1024]
#define SMEM_BYTES (K_B + ROWS * N_ * 2)   // 143,872 B

#define CLUSTER_SYNC() do { \
    asm volatile("barrier.cluster.arrive.aligned;" ::: "memory"); \
    asm volatile("barrier.cluster.wait.aligned;"   ::: "memory"); \
} while (0)

__device__ __forceinline__ uint32_t smem_u32_base(const void* p) {
    uint32_t a;
    asm("{ .reg .u64 t; cvta.to.shared.u64 t, %1; cvt.u32.u64 %0, t; }"
        : "=r"(a) : "l"(p));
    return a;
}
__device__ __forceinline__ uint32_t mapa_u32(uint32_t laddr, uint32_t rank) {
    uint32_t r;
    asm("mapa.shared::cluster.u32 %0, %1, %2;" : "=r"(r) : "r"(laddr), "r"(rank));
    return r;
}
__device__ __forceinline__ void st_cluster_u32(uint32_t addr, uint32_t v) {
    asm volatile("st.shared::cluster.u32 [%0], %1;" :: "r"(addr), "r"(v) : "memory");
}
__device__ __forceinline__ void st_cluster_f2(uint32_t addr, float2 v) {
    asm volatile("st.shared::cluster.v2.f32 [%0], {%1, %2};"
                 :: "r"(addr), "f"(v.x), "f"(v.y) : "memory");
}
__device__ __forceinline__ float2 ld_cluster_f2(uint32_t addr) {
    float2 v;
    asm volatile("ld.shared::cluster.v2.f32 {%0, %1}, [%2];"
                 : "=f"(v.x), "=f"(v.y) : "r"(addr) : "memory");
    return v;
}

__device__ __forceinline__ float wred(float x) {
    x += __shfl_xor_sync(0xffffffffu, x, 16);
    x += __shfl_xor_sync(0xffffffffu, x, 8);
    x += __shfl_xor_sync(0xffffffffu, x, 4);
    x += __shfl_xor_sync(0xffffffffu, x, 2);
    x += __shfl_xor_sync(0xffffffffu, x, 1);
    return x;
}

__global__ void __launch_bounds__(1024, 1)
rt_kernel(const float* __restrict__ Mn, float* __restrict__ out) {
    extern __shared__ float sm[];
    float*   z_s    = sm;                          // [1024]
    float*   u_s    = (float*)((char*)sm + U_B);   // [64]
    __half2* zh2    = (__half2*)((char*)sm + ZH2_B);
    __half2* wpart  = (__half2*)((char*)sm + WPART_B);   // [16*32]
    float2*  wpartf = (float2*)((char*)sm + WPARTF_B);   // [16*32]
    float2*  zsl    = (float2*)((char*)sm + ZSL_B);      // [32]
    __half*  Ksh    = (__half*)((char*)sm + K_B);        // [64*1024]
    __half2* Ks2    = (__half2*)Ksh;                     // [64*512]

    const uint32_t smb = smem_u32_base(sm);
    const int tid  = threadIdx.x;
    const int lane = tid & 31;
    const int warp = tid >> 5;
    const int b    = blockIdx.x / NCTA;
    const int pid  = blockIdx.x % NCTA;    // == cluster rank (1D x-major cluster)
    const int row0 = pid * ROWS;

    const float* Mb = Mn + (size_t)b * N_ * N_;

    // ---- Build K = exp(-lambda*min(M,5)) in fp16 SMEM (64 uniform rows) ----
    for (int li = 0; li < ROWS; li++) {
        const float m = Mb[(size_t)(row0 + li) * N_ + tid];
        Ksh[li * N_ + tid] = __float2half_rn(__expf(-LMB * fminf(m, 5.0f)));
    }
    if (tid < ROWS) u_s[tid] = RINV;
    __syncthreads();

    const float4* U4 = (const float4*)u_s;
    const __half2 h2zero = __float2half2_rn(0.f);
    const int o = tid >> 5, l = tid & 31;   // scatter/pull owner + slot (tid<512)

    for (int iter = 0; iter <= ITERS; iter++) {
        const bool fastI = (iter < PRECISE_FROM);

        // ---- Pass A: w[j] = sum_i K[i][j]*u[i]; thread t owns cols 2t,2t+1 ----
        if (tid < NP_) {
            float w0 = 0.f, w1 = 0.f;
            if (fastI) {
                #pragma unroll
                for (int q = 0; q < 16; q++) {
                    const float4 uu = U4[q];
                    const int r = q << 2;
                    __half2 a;
                    a = __hmul2(Ks2[(r+0)*NP_+tid], __float2half2_rn(uu.x));
                    a = __hfma2(Ks2[(r+1)*NP_+tid], __float2half2_rn(uu.y), a);
                    a = __hfma2(Ks2[(r+2)*NP_+tid], __float2half2_rn(uu.z), a);
                    a = __hfma2(Ks2[(r+3)*NP_+tid], __float2half2_rn(uu.w), a);
                    const float2 f = __half22float2(a);
                    w0 += f.x; w1 += f.y;
                }
            } else {                       // exact f32 path
                #pragma unroll
                for (int q = 0; q < 16; q++) {
                    const float4 uu = U4[q];
                    const int r = q << 2;
                    const float2 k0 = __half22float2(Ks2[(r+0)*NP_+tid]);
                    const float2 k1 = __half22float2(Ks2[(r+1)*NP_+tid]);
                    const float2 k2 = __half22float2(Ks2[(r+2)*NP_+tid]);
                    const float2 k3 = __half22float2(Ks2[(r+3)*NP_+tid]);
                    w0 += k0.x*uu.x + k1.x*uu.y + k2.x*uu.z + k3.x*uu.w;
                    w1 += k0.y*uu.x + k1.y*uu.y + k2.y*uu.z + k3.y*uu.w;
                }
            }
            // ---- DSMEM scatter: warp w's slice -> CTA w's wpart[pid][lane] ----
            if (iter < ITERS) {
                const __half2 hh = __floats2half2_rn(w0, w1);
                const uint32_t bits = *reinterpret_cast<const uint32_t*>(&hh);
                st_cluster_u32(mapa_u32(smb + WPART_B + (((uint32_t)pid << 5) + l) * 4, o), bits);
            } else {
                st_cluster_f2(mapa_u32(smb + WPARTF_B + (((uint32_t)pid << 5) + l) * 8, o),
                              make_float2(w0, w1));
            }
        }

        CLUSTER_SYNC();      // all slices delivered (arrive=release, wait=acquire)

        // ---- Owner reduce: 16 sources x 32 col-pairs -> z slice ----
        if (warp == 0) {
            float a0 = 0.f, a1 = 0.f;
            if (iter < ITERS) {
                #pragma unroll
                for (int q = 0; q < NCTA; q++) {
                    const float2 p = __half22float2(wpart[(q << 5) + lane]);
                    a0 += p.x; a1 += p.y;
                }
            } else {
                #pragma unroll
                for (int q = 0; q < NCTA; q++) {
                    const float2 p = wpartf[(q << 5) + lane];
                    a0 += p.x; a1 += p.y;
                }
            }
            zsl[lane] = make_float2(RINV / a0, RINV / a1);
        }

        CLUSTER_SYNC();      // all z slices published

        // ---- Pull: assemble full z locally (f32 + half2) ----
        if (tid < NP_) {
            const float2 zz = ld_cluster_f2(mapa_u32(smb + ZSL_B + (uint32_t)l * 8, o));
            ((float2*)z_s)[tid] = zz;
            zh2[tid] = __floats2half2_rn(zz.x, zz.y);
        }
        __syncthreads();

        if (iter == ITERS) break;          // z_s now holds v (f32, exact exchange)

        // ---- Pass B: 32 warps x 2 rows; u[i] = r / (K z)[i] ----
        const int rb = warp << 1;
        float t0 = 0.f, t1 = 0.f;
        if (fastI) {
            #pragma unroll
            for (int ch = 0; ch < 4; ch++) {
                __half2 a0 = h2zero, a1 = h2zero;
                #pragma unroll
                for (int kk = 0; kk < 4; kk++) {
                    const int c2 = lane + (((ch << 2) + kk) << 5);
                    const __half2 zz = zh2[c2];
                    a0 = __hfma2(Ks2[(rb+0)*NP_+c2], zz, a0);
                    a1 = __hfma2(Ks2[(rb+1)*NP_+c2], zz, a1);
                }
                float2 f;
                f = __half22float2(a0); t0 += f.x + f.y;
                f = __half22float2(a1); t1 += f.x + f.y;
            }
        } else {                           // exact f32 path
            #pragma unroll 4
            for (int k = 0; k < 16; k++) {
                const int c2 = lane + (k << 5);
                const float2 zz = ((const float2*)z_s)[c2];
                const float2 k0 = __half22float2(Ks2[(rb+0)*NP_+c2]);
                const float2 k1 = __half22float2(Ks2[(rb+1)*NP_+c2]);
                t0 += k0.x*zz.x + k0.y*zz.y;
                t1 += k1.x*zz.x + k1.y*zz.y;
            }
        }
        t0 = wred(t0); t1 = wred(t1);
        if (lane == 0) {
            u_s[rb + 0] = RINV / t0;
            u_s[rb + 1] = RINV / t1;
        }
        __syncthreads();                   // u_s ready for next pass A
    }

    CLUSTER_SYNC();   // final remote reads complete before any peer may exit

    // ---- Epilogue: P[i][j] = u[i] * K32[i][j] * v[j] (f32 __expf recompute) ----
    const float vj = z_s[tid];
    float* outb = out + (size_t)b * N_ * N_;
    #pragma unroll 4
    for (int li = 0; li < ROWS; li++) {
        const float m = Mb[(size_t)(row0 + li) * N_ + tid];
        const float k = __expf(-LMB * fminf(m, 5.0f));
        outb[(size_t)(row0 + li) * N_ + tid] = u_s[li] * k * vj;
    }
}

extern "C" void kernel_launch(void* const* d_in, const int* in_sizes, int n_in,
                              void* d_out, int out_size) {
    const float* M = (const float*)d_in[0];
    float* out = (float*)d_out;

    static bool attr_set = false;
    if (!attr_set) {
        cudaFuncSetAttribute(rt_kernel, cudaFuncAttributeMaxDynamicSharedMemorySize, SMEM_BYTES);
        cudaFuncSetAttribute(rt_kernel, cudaFuncAttributeNonPortableClusterSizeAllowed, 1);
        attr_set = true;
    }

    cudaLaunchConfig_t cfg = {};
    cfg.gridDim  = dim3(GRID_, 1, 1);
    cfg.blockDim = dim3(1024, 1, 1);
    cfg.dynamicSmemBytes = SMEM_BYTES;
    cfg.stream = 0;
    cudaLaunchAttribute attrs[1];
    attrs[0].id = cudaLaunchAttributeClusterDimension;
    attrs[0].val.clusterDim.x = NCTA;
    attrs[0].val.clusterDim.y = 1;
    attrs[0].val.clusterDim.z = 1;
    cfg.attrs = attrs;
    cfg.numAttrs = 1;

    cudaLaunchKernelEx(&cfg, rt_kernel, M, out);
}

// round 17
// speedup vs baseline: 1.6296x; 1.6296x over previous
#include <cuda_runtime.h>
#include <cuda_fp16.h>
#include <math.h>

#define B_       8
#define N_       1024
#define NP_      512           // column pairs
#define NCTA     18            // CTAs per batch
#define GRID_    (B_ * NCTA)   // 144 <= 148 SMs -> all co-resident at 1 CTA/SM
#define ROWS_MAX 57            // ceil(1024/18)
#define ITERS    8             // residual ladder calibrated q~0.23, C~1:
                               // q^8 ~ 7.7e-6 < fp16 noise floor ~1.9e-5
#define PRECISE_FROM (ITERS - 2)   // iters >= this use exact f32 math paths
#define RINV     (1.0f / 1024.0f)
#define LMB      10.0f

// Ping-ponged half2 partials (one barrier/iter; ping-pong makes reuse safe)
__device__ __half2      g_ph[2][B_][NCTA][NP_];
// fp32 partials for the final (v-producing) pass
__device__ float2       g_pf[B_][NCTA][NP_];
// Monotonic per-batch barrier counters (reset each launch)
__device__ unsigned int g_bar[B_];

__global__ void rt_init() {
    if (threadIdx.x < B_) g_bar[threadIdx.x] = 0u;
}

__device__ __forceinline__ float wred(float x) {
    x += __shfl_xor_sync(0xffffffffu, x, 16);
    x += __shfl_xor_sync(0xffffffffu, x, 8);
    x += __shfl_xor_sync(0xffffffffu, x, 4);
    x += __shfl_xor_sync(0xffffffffu, x, 2);
    x += __shfl_xor_sync(0xffffffffu, x, 1);
    return x;
}

// Per-batch multi-CTA barrier: release -> arrive -> spin -> acquire.
// (central atomic + single poller per CTA — empirically fastest form;
//  beats both 18-poller flag arrays (R7) and barrier.cluster+L1-flush (R14))
__device__ __forceinline__ void batch_barrier(int b, int tid, unsigned int* gen) {
    (*gen)++;
    __syncthreads();
    if (tid == 0) {
        __threadfence();
        atomicAdd(&g_bar[b], 1u);
        const unsigned int tgt = (*gen) * NCTA;
        volatile unsigned int* bp = &g_bar[b];
        while (*bp < tgt) { __nanosleep(20); }
        __threadfence();
    }
    __syncthreads();
}

__global__ void __launch_bounds__(1024, 1)
rt_kernel(const float* __restrict__ Mn, float* __restrict__ out) {
    extern __shared__ float sm[];
    float*   z_s  = sm;                          // [1024] f32 z (float2-aligned)
    float*   u_s  = sm + N_;                     // [64]   f32 u
    __half2* zh2  = (__half2*)(sm + N_ + 64);    // [512]  z as half2
    __half*  Ksh  = (__half*)(zh2 + NP_);        // [57*1024] K fp16
    __half2* Ks2  = (__half2*)Ksh;               // [57*512]  K half2 pairs

    const int tid  = threadIdx.x;
    const int lane = tid & 31;
    const int warp = tid >> 5;
    const int b    = blockIdx.x / NCTA;
    const int pid  = blockIdx.x % NCTA;
    const int row0 = pid * ROWS_MAX;
    const int nrows = min(ROWS_MAX, N_ - row0);  // 57, last CTA: 55

    const float* Mb = Mn + (size_t)b * N_ * N_;

    // ---- Build K = exp(-lambda*min(M,5)) in fp16 SMEM (__expf: err ~3.6e-6,
    //      invisible under fp16 quantization 4.9e-4) ----
    for (int li = 0; li < ROWS_MAX; li++) {
        float k = 0.f;
        if (li < nrows) {
            float m = Mb[(size_t)(row0 + li) * N_ + tid];
            k = __expf(-LMB * fminf(m, 5.0f));
        }
        Ksh[li * N_ + tid] = __float2half_rn(k);   // zero rows beyond nrows
    }
    if (tid < 64) u_s[tid] = (tid < nrows) ? RINV : 0.f;
    __syncthreads();

    const float4* U4 = (const float4*)u_s;
    const __half2 h2zero = __float2half2_rn(0.f);
    unsigned int gen = 0;

    for (int iter = 0; iter <= ITERS; iter++) {
        const int  buf   = iter & 1;
        const bool fastI = (iter < PRECISE_FROM);

        // ---- Pass A: w[j] = sum_i K[i][j]*u[i], thread t owns cols 2t,2t+1 ----
        if (tid < NP_) {
            float w0 = 0.f, w1 = 0.f;
            if (fastI) {
                #pragma unroll
                for (int q = 0; q < 14; q++) {           // rows 0..55, 4 per chunk
                    const float4 uu = U4[q];
                    const int r = q << 2;
                    __half2 a;
                    a = __hmul2(Ks2[(r+0)*NP_+tid], __float2half2_rn(uu.x));
                    a = __hfma2(Ks2[(r+1)*NP_+tid], __float2half2_rn(uu.y), a);
                    a = __hfma2(Ks2[(r+2)*NP_+tid], __float2half2_rn(uu.z), a);
                    a = __hfma2(Ks2[(r+3)*NP_+tid], __float2half2_rn(uu.w), a);
                    const float2 f = __half22float2(a);
                    w0 += f.x; w1 += f.y;
                }
            } else {                                     // exact f32 path
                #pragma unroll
                for (int q = 0; q < 14; q++) {
                    const float4 uu = U4[q];
                    const int r = q << 2;
                    const float2 k0 = __half22float2(Ks2[(r+0)*NP_+tid]);
                    const float2 k1 = __half22float2(Ks2[(r+1)*NP_+tid]);
                    const float2 k2 = __half22float2(Ks2[(r+2)*NP_+tid]);
                    const float2 k3 = __half22float2(Ks2[(r+3)*NP_+tid]);
                    w0 += k0.x*uu.x + k1.x*uu.y + k2.x*uu.z + k3.x*uu.w;
                    w1 += k0.y*uu.x + k1.y*uu.y + k2.y*uu.z + k3.y*uu.w;
                }
            }
            {   // row 56 (always f32, cheap)
                const float u56 = u_s[56];
                const float2 k = __half22float2(Ks2[56*NP_+tid]);
                w0 += k.x * u56;  w1 += k.y * u56;
            }
            if (iter < ITERS) __stcg(&g_ph[buf][b][pid][tid], __floats2half2_rn(w0, w1));
            else              __stcg(&g_pf[b][pid][tid], make_float2(w0, w1));
        }

        batch_barrier(b, tid, &gen);     // all partials visible

        // ---- Reduce partials -> z pair, publish f32 + half2 ----
        if (tid < NP_) {
            float a0 = 0.f, a1 = 0.f;
            if (iter < ITERS) {
                #pragma unroll
                for (int q = 0; q < NCTA; q++) {
                    const float2 p = __half22float2(__ldcg(&g_ph[buf][b][q][tid]));
                    a0 += p.x; a1 += p.y;
                }
            } else {
                #pragma unroll
                for (int q = 0; q < NCTA; q++) {
                    const float2 p = __ldcg(&g_pf[b][q][tid]);
                    a0 += p.x; a1 += p.y;
                }
            }
            const float z0 = RINV / a0, z1 = RINV / a1;
            ((float2*)z_s)[tid] = make_float2(z0, z1);
            zh2[tid] = __floats2half2_rn(z0, z1);
        }
        __syncthreads();

        if (iter == ITERS) break;        // z_s now holds v (f32)

        // ---- Pass B: t[i] = sum_j K[i][j] z[j]; u[i] = r/t[i] ----
        if (warp < 14) {                 // rows 4w..4w+3 (0..55)
            const int rb = warp << 2;
            float t0 = 0.f, t1 = 0.f, t2 = 0.f, t3 = 0.f;
            if (fastI) {
                #pragma unroll
                for (int ch = 0; ch < 4; ch++) {
                    __half2 a0 = h2zero, a1 = h2zero, a2 = h2zero, a3 = h2zero;
                    #pragma unroll
                    for (int kk = 0; kk < 4; kk++) {
                        const int c2 = lane + (((ch << 2) + kk) << 5);
                        const __half2 zz = zh2[c2];
                        a0 = __hfma2(Ks2[(rb+0)*NP_+c2], zz, a0);
                        a1 = __hfma2(Ks2[(rb+1)*NP_+c2], zz, a1);
                        a2 = __hfma2(Ks2[(rb+2)*NP_+c2], zz, a2);
                        a3 = __hfma2(Ks2[(rb+3)*NP_+c2], zz, a3);
                    }
                    float2 f;
                    f = __half22float2(a0); t0 += f.x + f.y;
                    f = __half22float2(a1); t1 += f.x + f.y;
                    f = __half22float2(a2); t2 += f.x + f.y;
                    f = __half22float2(a3); t3 += f.x + f.y;
                }
            } else {                     // exact f32 path
                #pragma unroll 4
                for (int k = 0; k < 16; k++) {
                    const int c2 = lane + (k << 5);
                    const float2 zz = ((const float2*)z_s)[c2];
                    const float2 k0 = __half22float2(Ks2[(rb+0)*NP_+c2]);
                    const float2 k1 = __half22float2(Ks2[(rb+1)*NP_+c2]);
                    const float2 k2 = __half22float2(Ks2[(rb+2)*NP_+c2]);
                    const float2 k3 = __half22float2(Ks2[(rb+3)*NP_+c2]);
                    t0 += k0.x*zz.x + k0.y*zz.y;
                    t1 += k1.x*zz.x + k1.y*zz.y;
                    t2 += k2.x*zz.x + k2.y*zz.y;
                    t3 += k3.x*zz.x + k3.y*zz.y;
                }
            }
            t0 = wred(t0); t1 = wred(t1); t2 = wred(t2); t3 = wred(t3);
            if (lane == 0) {
                u_s[rb + 0] = (rb + 0 < nrows) ? RINV / t0 : 0.f;
                u_s[rb + 1] = (rb + 1 < nrows) ? RINV / t1 : 0.f;
                u_s[rb + 2] = (rb + 2 < nrows) ? RINV / t2 : 0.f;
                u_s[rb + 3] = (rb + 3 < nrows) ? RINV / t3 : 0.f;
            }
        } else if (warp == 14) {         // row 56 (f32 always)
            float t56 = 0.f;
            #pragma unroll 4
            for (int k = 0; k < 16; k++) {
                const int c2 = lane + (k << 5);
                const float2 zz = ((const float2*)z_s)[c2];
                const float2 kk = __half22float2(Ks2[56*NP_+c2]);
                t56 += kk.x*zz.x + kk.y*zz.y;
            }
            t56 = wred(t56);
            if (lane == 0) u_s[56] = (56 < nrows) ? RINV / t56 : 0.f;
        }
        __syncthreads();                 // u_s ready for next pass A
    }

    // ---- Epilogue: P[i][j] = u[i] * K32[i][j] * v[j], K recomputed in f32
    //      via __expf (err ~3.6e-6 rel, 300x under the 1e-3 threshold) ----
    const float vj = z_s[tid];           // v for column tid (f32 final pass)
    float* outb = out + (size_t)b * N_ * N_;
    #pragma unroll 4
    for (int li = 0; li < nrows; li++) {
        const float m = Mb[(size_t)(row0 + li) * N_ + tid];
        const float k = __expf(-LMB * fminf(m, 5.0f));
        outb[(size_t)(row0 + li) * N_ + tid] = u_s[li] * k * vj;
    }
}

extern "C" void kernel_launch(void* const* d_in, const int* in_sizes, int n_in,
                              void* d_out, int out_size) {
    const float* M = (const float*)d_in[0];
    float* out = (float*)d_out;

    // z(4KB) + u(256B) + zh2(2KB) + K fp16 (116736B) = 123,136 B
    const int smem_bytes = (N_ + 64) * (int)sizeof(float)
                         + NP_ * (int)sizeof(__half2)
                         + ROWS_MAX * N_ * (int)sizeof(__half);
    static bool attr_set = false;
    if (!attr_set) {
        cudaFuncSetAttribute(rt_kernel, cudaFuncAttributeMaxDynamicSharedMemorySize, smem_bytes);
        attr_set = true;
    }

    rt_init<<<1, 32>>>();
    rt_kernel<<<GRID_, 1024, smem_bytes>>>(M, out);
}